// round 17
// baseline (speedup 1.0000x reference)
#include <cuda_runtime.h>
#include <cuda_bf16.h>
#include <mma.h>

using namespace nvcuda;

#define NN 100000
#define NE 600000
#define NG 256
#define HID 128
#define BN_EPS 1e-5f

// ---------------- scratch (device globals; no allocation allowed) ------------
__device__ float g_deg[NN];
__device__ float g_dinv[NN];
__device__ float g_xa[NN * 8];     // aggregated 7-dim input features (padded to 8)
__device__ float g_hl[NN * HID];   // hl = h @ W
__device__ float g_agg[NN * HID];  // aggregated messages (pre-activation)
__device__ float g_lig[NG * HID];  // pooled per-graph embedding
__device__ float g_p[64];          // pocket MLP output

// vectorized global reduction (sm_90+, PTX ISA 8.1)
__device__ __forceinline__ void red_add_v4(float* addr, float4 v) {
    asm volatile("red.global.add.v4.f32 [%0], {%1,%2,%3,%4};"
                 :: "l"(addr), "f"(v.x), "f"(v.y), "f"(v.z), "f"(v.w)
                 : "memory");
}

// split a fragment into tf32 big + small parts (3xTF32 precision recovery)
#define SPLIT_TF32(bigf, smallf)                                   \
    _Pragma("unroll")                                              \
    for (int _i = 0; _i < (bigf).num_elements; ++_i) {             \
        float _v = (bigf).x[_i];                                   \
        float _b = wmma::__float_to_tf32(_v);                      \
        (bigf).x[_i] = _b;                                         \
        (smallf).x[_i] = wmma::__float_to_tf32(_v - _b);           \
    }

// ---------------- degree / normalization ------------------------------------
__global__ void k_deg_init() {
    int n = blockIdx.x * blockDim.x + threadIdx.x;
    if (n < NN) g_deg[n] = 1.0f;  // self-loop
}

__global__ void k_deg_edges(const int* __restrict__ ei) {
    int e = blockIdx.x * blockDim.x + threadIdx.x;
    if (e < NE) atomicAdd(&g_deg[ei[NE + e]], 1.0f);
}

__global__ void k_dinv() {
    int n = blockIdx.x * blockDim.x + threadIdx.x;
    if (n < NN) g_dinv[n] = rsqrtf(g_deg[n]);
}

// ------- layer-0 feature aggregation on raw 7-dim x (exact reordering) -------
__global__ void k_xa_init(const float* __restrict__ x) {
    int n = blockIdx.x * blockDim.x + threadIdx.x;
    if (n >= NN) return;
    float d = g_dinv[n]; float d2 = d * d;
#pragma unroll
    for (int c = 0; c < 7; ++c) g_xa[n * 8 + c] = x[n * 7 + c] * d2;
    g_xa[n * 8 + 7] = 0.f;
}

// xa[dst] += x[src] * dinv[src]*dinv[dst]; 2 threads per edge (4 channels each)
__global__ __launch_bounds__(256) void k_xa_edges(const float* __restrict__ x,
                                                  const int* __restrict__ ei) {
    int t = blockIdx.x * blockDim.x + threadIdx.x;
    int e = t >> 1;
    int half = t & 1;
    if (e >= NE) return;
    int src = __ldg(&ei[e]);
    int dst = __ldg(&ei[NE + e]);
    float nm = __ldg(&g_dinv[src]) * __ldg(&g_dinv[dst]);
    float4 v;
    if (half == 0) {
        v.x = __ldg(&x[src * 7 + 0]) * nm;
        v.y = __ldg(&x[src * 7 + 1]) * nm;
        v.z = __ldg(&x[src * 7 + 2]) * nm;
        v.w = __ldg(&x[src * 7 + 3]) * nm;
    } else {
        v.x = __ldg(&x[src * 7 + 4]) * nm;
        v.y = __ldg(&x[src * 7 + 5]) * nm;
        v.z = __ldg(&x[src * 7 + 6]) * nm;
        v.w = 0.f;
    }
    red_add_v4(&g_xa[(size_t)dst * 8 + half * 4], v);
}

// ---------------- layer 0 GEMM: xa[N,7] @ W0[7,128] -> g_agg -----------------
__global__ __launch_bounds__(256) void k_gemm0(const float* __restrict__ W0) {
    int idx = blockIdx.x * blockDim.x + threadIdx.x;
    int n = idx >> 5;
    int cg = idx & 31;
    if (n >= NN) return;
    float4 acc = make_float4(0.f, 0.f, 0.f, 0.f);
    const float4* W4 = (const float4*)W0;
#pragma unroll
    for (int k = 0; k < 7; ++k) {
        float xv = g_xa[(size_t)n * 8 + k];
        float4 w = __ldg(&W4[k * 32 + cg]);
        acc.x += xv * w.x; acc.y += xv * w.y; acc.z += xv * w.z; acc.w += xv * w.w;
    }
    ((float4*)g_agg)[(size_t)n * 32 + cg] = acc;
}

// ------------- main GEMM on tensor cores (split-tf32 / 3xTF32) ---------------
// A = relu(g_agg * ss + st) (prev layer bias+BN+ReLU fused on load)
// C = A @ W via wmma m16n16k8 tf32, 3 products for ~fp32 precision.
// Epilogue: hl = C (store_matrix_sync), then agg = hl * dinv^2.
// Block: 128x128 output tile, 8 warps in 2(m) x 4(n) grid; warp tile 64x32.
#define AS_LD 36   // padded lda (floats); 36*4=144B, multiple of 16B for wmma
__global__ __launch_bounds__(256) void k_gemm128(const float* __restrict__ W,
                                                 const float* __restrict__ gamma,
                                                 const float* __restrict__ beta,
                                                 const float* __restrict__ mean,
                                                 const float* __restrict__ var,
                                                 const float* __restrict__ bias) {
    __shared__ float As[128 * AS_LD];  // [row][k] 128x32, padded
    __shared__ float Ws[32 * 128];     // [k][c]
    __shared__ float ss[128], st[128];
    int tid = threadIdx.x;
    int row0 = blockIdx.x * 128;
    int wid = tid >> 5;
    int warp_m = wid >> 2;   // 0..1 -> 64 rows each
    int warp_n = wid & 3;    // 0..3 -> 32 cols each

    if (tid < 128) {
        float s = gamma[tid] * rsqrtf(var[tid] + BN_EPS);
        ss[tid] = s;
        st[tid] = (bias[tid] - mean[tid]) * s + beta[tid];
    }
    __syncthreads();

    wmma::fragment<wmma::accumulator, 16, 16, 8, float> acc[4][2];
#pragma unroll
    for (int mt = 0; mt < 4; ++mt)
#pragma unroll
        for (int nt = 0; nt < 2; ++nt) wmma::fill_fragment(acc[mt][nt], 0.f);

    int lr = tid >> 3;             // 0..31 (row within load group)
    int lk = (tid & 7) * 4;        // 0,4,...,28
    int wk = tid >> 5;             // 0..7
    int wc = (tid & 31) * 4;       // 0..124

    for (int kc = 0; kc < 4; ++kc) {
        int c0 = kc * 32 + lk;     // channel of first loaded element
        // stage A chunk (with fused activation) and W chunk
#pragma unroll
        for (int l = 0; l < 4; ++l) {
            int r = l * 32 + lr;
            int gr = row0 + r;
            float4 v = make_float4(0.f, 0.f, 0.f, 0.f);
            if (gr < NN) {
                float4 a = *(const float4*)&g_agg[(size_t)gr * 128 + c0];
                v.x = fmaxf(a.x * ss[c0 + 0] + st[c0 + 0], 0.f);
                v.y = fmaxf(a.y * ss[c0 + 1] + st[c0 + 1], 0.f);
                v.z = fmaxf(a.z * ss[c0 + 2] + st[c0 + 2], 0.f);
                v.w = fmaxf(a.w * ss[c0 + 3] + st[c0 + 3], 0.f);
            }
            As[r * AS_LD + lk + 0] = v.x;
            As[r * AS_LD + lk + 1] = v.y;
            As[r * AS_LD + lk + 2] = v.z;
            As[r * AS_LD + lk + 3] = v.w;
        }
#pragma unroll
        for (int l = 0; l < 4; ++l) {
            int k = l * 8 + wk;
            *(float4*)&Ws[k * 128 + wc] = *(const float4*)&W[(kc * 32 + k) * 128 + wc];
        }
        __syncthreads();

#pragma unroll
        for (int kt = 0; kt < 4; ++kt) {
            int k0 = kt * 8;
            wmma::fragment<wmma::matrix_b, 16, 16, 8, wmma::precision::tf32,
                           wmma::row_major> bb[2], bs[2];
#pragma unroll
            for (int nt = 0; nt < 2; ++nt) {
                wmma::load_matrix_sync(bb[nt], &Ws[k0 * 128 + warp_n * 32 + nt * 16], 128);
                SPLIT_TF32(bb[nt], bs[nt]);
            }
#pragma unroll
            for (int mt = 0; mt < 4; ++mt) {
                wmma::fragment<wmma::matrix_a, 16, 16, 8, wmma::precision::tf32,
                               wmma::row_major> ab, as_;
                wmma::load_matrix_sync(ab, &As[(warp_m * 64 + mt * 16) * AS_LD + k0], AS_LD);
                SPLIT_TF32(ab, as_);
#pragma unroll
                for (int nt = 0; nt < 2; ++nt) {
                    wmma::mma_sync(acc[mt][nt], ab, bb[nt], acc[mt][nt]);
                    wmma::mma_sync(acc[mt][nt], ab, bs[nt], acc[mt][nt]);
                    wmma::mma_sync(acc[mt][nt], as_, bb[nt], acc[mt][nt]);
                }
            }
        }
        __syncthreads();
    }

    // epilogue: store hl tiles (NN % 16 == 0 -> tiles fully in or out)
#pragma unroll
    for (int mt = 0; mt < 4; ++mt) {
        int gr = row0 + warp_m * 64 + mt * 16;
        if (gr < NN) {
#pragma unroll
            for (int nt = 0; nt < 2; ++nt) {
                wmma::store_matrix_sync(&g_hl[(size_t)gr * 128 + warp_n * 32 + nt * 16],
                                        acc[mt][nt], 128, wmma::mem_row_major);
            }
        }
    }
    __syncthreads();  // global writes visible block-wide

    // agg = hl * dinv^2 (self-loop init); 2 threads per row, 16 float4 each
    {
        int r = tid >> 1;
        int half = tid & 1;
        int gr = row0 + r;
        if (gr < NN) {
            float sn = g_dinv[gr]; sn *= sn;
            const float4* src = (const float4*)&g_hl[(size_t)gr * 128 + half * 64];
            float4* dst = (float4*)&g_agg[(size_t)gr * 128 + half * 64];
#pragma unroll
            for (int i = 0; i < 16; ++i) {
                float4 v = src[i];
                dst[i] = make_float4(v.x * sn, v.y * sn, v.z * sn, v.w * sn);
            }
        }
    }
}

// ---------------- edge scatter: agg[dst] += hl[src] * dinv[src]*dinv[dst] ---
__global__ __launch_bounds__(256) void k_edges(const int* __restrict__ ei) {
    int gt = blockIdx.x * blockDim.x + threadIdx.x;
    int e = gt >> 5;
    int lane = gt & 31;
    if (e >= NE) return;
    int src = __ldg(&ei[e]);
    int dst = __ldg(&ei[NE + e]);
    float nm = __ldg(&g_dinv[src]) * __ldg(&g_dinv[dst]);
    float4 v = __ldg(&((const float4*)g_hl)[(size_t)src * 32 + lane]);
    v.x *= nm; v.y *= nm; v.z *= nm; v.w *= nm;
    red_add_v4(&g_agg[(size_t)dst * 128 + lane * 4], v);
}

// ------- mean pool per graph with fused layer-2 bias+BN+ReLU -----------------
__global__ void k_pool(const int* __restrict__ batch,
                       const float* __restrict__ gamma, const float* __restrict__ beta,
                       const float* __restrict__ mean, const float* __restrict__ var,
                       const float* __restrict__ bias) {
    int g = blockIdx.x;
    int c = threadIdx.x;  // 128 threads, c = channel
    __shared__ int s_lo, s_hi;
    if (c == 0) {
        int lo = 0, hi = NN;
        while (lo < hi) { int m = (lo + hi) >> 1; if (batch[m] < g) lo = m + 1; else hi = m; }
        s_lo = lo;
        int l2 = lo, h2 = NN;
        while (l2 < h2) { int m = (l2 + h2) >> 1; if (batch[m] < g + 1) l2 = m + 1; else h2 = m; }
        s_hi = l2;
    }
    float s = gamma[c] * rsqrtf(var[c] + BN_EPS);
    float t = (bias[c] - mean[c]) * s + beta[c];
    __syncthreads();
    int lo = s_lo, hi = s_hi;
    float sum = 0.f;
    for (int r = lo; r < hi; ++r)
        sum += fmaxf(g_agg[(size_t)r * 128 + c] * s + t, 0.f);
    float cnt = (float)(hi - lo);
    g_lig[g * 128 + c] = sum / fmaxf(cnt, 1.0f);
}

// ---------------- pocket MLP: 28 -> 64 -> 64 --------------------------------
__global__ void k_pocket(const float* __restrict__ pocket,
                         const float* __restrict__ pw1, const float* __restrict__ pb1,
                         const float* __restrict__ pw2, const float* __restrict__ pb2) {
    __shared__ float z[64];
    int j = threadIdx.x;  // 64 threads
    float a = pb1[j];
#pragma unroll
    for (int k = 0; k < 28; ++k) a += pocket[k] * pw1[k * 64 + j];
    z[j] = fmaxf(a, 0.f);
    __syncthreads();
    float b = pb2[j];
#pragma unroll 8
    for (int k = 0; k < 64; ++k) b += z[k] * pw2[k * 64 + j];
    g_p[j] = b;
}

// ---------------- classifier: [lig|p] (192) -> 96 -> 1 ----------------------
__global__ void k_cls(const float* __restrict__ cw1, const float* __restrict__ cb1,
                      const float* __restrict__ cw2, const float* __restrict__ cb2,
                      float* __restrict__ out) {
    int g = blockIdx.x;
    int j = threadIdx.x;  // 96 threads
    __shared__ float emb[192];
    __shared__ float red[96];
    for (int k = j; k < 128; k += 96) emb[k] = g_lig[g * 128 + k];
    if (j < 64) emb[128 + j] = g_p[j];
    __syncthreads();
    float a = cb1[j];
#pragma unroll 8
    for (int k = 0; k < 192; ++k) a += emb[k] * cw1[k * 96 + j];
    red[j] = fmaxf(a, 0.f) * cw2[j];
    __syncthreads();
    if (j < 32) {
        float s = red[j] + red[j + 32] + red[j + 64];
#pragma unroll
        for (int o = 16; o > 0; o >>= 1) s += __shfl_down_sync(0xFFFFFFFFu, s, o);
        if (j == 0) out[g] = s + cb2[0];
    }
}

// ---------------------------------------------------------------------------
extern "C" void kernel_launch(void* const* d_in, const int* in_sizes, int n_in,
                              void* d_out, int out_size) {
    const float* x      = (const float*)d_in[0];
    const int*   ei     = (const int*)d_in[1];
    const int*   batch  = (const int*)d_in[2];
    const float* pocket = (const float*)d_in[3];
    const float* W0 = (const float*)d_in[4];
    const float* b0 = (const float*)d_in[5];
    const float* W1 = (const float*)d_in[6];
    const float* b1 = (const float*)d_in[7];
    const float* W2 = (const float*)d_in[8];
    const float* b2 = (const float*)d_in[9];
    const float* bn_gamma = (const float*)d_in[10];
    const float* bn_beta  = (const float*)d_in[11];
    const float* bn_mean  = (const float*)d_in[12];
    const float* bn_var   = (const float*)d_in[13];
    const float* pw1 = (const float*)d_in[14];
    const float* pb1 = (const float*)d_in[15];
    const float* pw2 = (const float*)d_in[16];
    const float* pb2 = (const float*)d_in[17];
    const float* cw1 = (const float*)d_in[18];
    const float* cb1 = (const float*)d_in[19];
    const float* cw2 = (const float*)d_in[20];
    const float* cb2 = (const float*)d_in[21];
    float* out = (float*)d_out;

    const int TPB = 256;
    int gN   = (NN + TPB - 1) / TPB;
    int gE   = (NE + TPB - 1) / TPB;
    int gE2  = (NE * 2 + TPB - 1) / TPB;
    int gN32 = (NN * 32 + TPB - 1) / TPB;
    int gE32 = (NE * 32 + TPB - 1) / TPB;
    int gG   = (NN + 127) / 128;

    // normalization coefficients
    k_deg_init<<<gN, TPB>>>();
    k_deg_edges<<<gE, TPB>>>(ei);
    k_dinv<<<gN, TPB>>>();

    // layer 0: aggregate raw 7-dim features first (A(xW) == (Ax)W), then GEMM
    k_xa_init<<<gN, TPB>>>(x);
    k_xa_edges<<<gE2, TPB>>>(x, ei);
    k_gemm0<<<gN32, TPB>>>(W0);

    // layer 1: gemm applies layer-0 bias/BN/ReLU on input (tensor cores)
    k_gemm128<<<gG, TPB>>>(W1, bn_gamma + 0 * HID, bn_beta + 0 * HID,
                           bn_mean + 0 * HID, bn_var + 0 * HID, b0);
    k_edges<<<gE32, TPB>>>(ei);

    // layer 2: gemm applies layer-1 bias/BN/ReLU on input (tensor cores)
    k_gemm128<<<gG, TPB>>>(W2, bn_gamma + 1 * HID, bn_beta + 1 * HID,
                           bn_mean + 1 * HID, bn_var + 1 * HID, b1);
    k_edges<<<gE32, TPB>>>(ei);

    // readout: pool applies layer-2 bias/BN/ReLU on input
    k_pool<<<NG, 128>>>(batch, bn_gamma + 2 * HID, bn_beta + 2 * HID,
                        bn_mean + 2 * HID, bn_var + 2 * HID, b2);
    k_pocket<<<1, 64>>>(pocket, pw1, pb1, pw2, pb2);
    k_cls<<<NG, 96>>>(cw1, cb1, cw2, cb2, out);
}